// round 12
// baseline (speedup 1.0000x reference)
#include <cuda_runtime.h>
#include <cuda_fp16.h>
#include <cuda_bf16.h>

// Problem constants
#define Nn   50000
#define Ee   800000
#define Dd   128
#define Hh   8
#define HIDd 512
#define SLOPEf 0.2f
#define EPSf 1e-5f
#define MT   391          // ceil(50000/128) row tiles

// featM smem layout (3-term: Ah Al Bh Bl)
#define OFF_AL 34816
#define OFF_BH 69632
#define OFF_BL 104448
#define SM_FEAT 139264
// gemm2 smem layout (Ah Al Bh + BN consts)
#define G2_AL 34816
#define G2_BH 69632
#define G2_SC 104448
#define G2_SH 104960
#define SM_G2 105472
// gemm3 smem layout (Ah Bh Bl + stats)
#define G3_BH 34816
#define G3_BL 69632
#define G3_ST 104448
#define SM_G3 105472

// ---------------- device scratch ----------------
__device__ __align__(16) float    g_feat[Nn * Dd];
__device__ __align__(16) float    g_el[Nn * Hh];
__device__ __align__(16) float    g_er[Nn * Hh];
__device__ __align__(16) float    g_agg[Nn * Dd];
__device__ __align__(16) float    g_h2[Nn * Dd];
// CSR
__device__ int g_deg[Nn];
__device__ int g_startA[Nn];
__device__ int g_cursor[Nn];
__device__ int g_csrc[Ee];
__device__ int g_total;
// prepared fp16-split weights, [tile][n][k] k-contiguous
__device__ __align__(16) __half g_Wp_h[Dd * Dd],    g_Wp_l[Dd * Dd];
__device__ __align__(16) __half g_W1p_h[Dd * HIDd];
__device__ __align__(16) __half g_W2p_h[HIDd * Dd], g_W2p_l[HIDd * Dd];
// hidden activations, fp16 hi plane only, [row][512]
__device__ __align__(16) __half g_hid_h[(size_t)Nn * HIDd];
__device__ double g_sum1[Dd], g_sq1[Dd], g_sum2[Dd], g_sq2[Dd];

// ---------------- small helpers ----------------
__device__ __forceinline__ unsigned smem_u32(const void* p) {
    unsigned a;
    asm("{ .reg .u64 t; cvta.to.shared.u64 t, %1; cvt.u32.u64 %0, t; }" : "=r"(a) : "l"(p));
    return a;
}
__device__ __forceinline__ void split_store4(__half* dh, __half* dl, float4 v) {
    __half2 h0 = __floats2half2_rn(v.x, v.y);
    __half2 h1 = __floats2half2_rn(v.z, v.w);
    float2 f0 = __half22float2(h0);
    float2 f1 = __half22float2(h1);
    __half2 l0 = __floats2half2_rn(v.x - f0.x, v.y - f0.y);
    __half2 l1 = __floats2half2_rn(v.z - f1.x, v.w - f1.y);
    *(__half2*)(dh)     = h0;  *(__half2*)(dh + 2) = h1;
    *(__half2*)(dl)     = l0;  *(__half2*)(dl + 2) = l1;
}

// ---------------- mma.sync primitives ----------------
#define LDSM4(r, a) asm volatile("ldmatrix.sync.aligned.m8n8.x4.shared.b16 {%0,%1,%2,%3}, [%4];" \
    : "=r"((r)[0]), "=r"((r)[1]), "=r"((r)[2]), "=r"((r)[3]) : "r"(a))
#define LDSM2(r, a) asm volatile("ldmatrix.sync.aligned.m8n8.x2.shared.b16 {%0,%1}, [%2];" \
    : "=r"((r)[0]), "=r"((r)[1]) : "r"(a))

__device__ __forceinline__ void mma_f16(float c[4], const unsigned a[4], const unsigned b[2]) {
    asm volatile("mma.sync.aligned.m16n8k16.row.col.f32.f16.f16.f32 "
        "{%0,%1,%2,%3}, {%4,%5,%6,%7}, {%8,%9}, {%0,%1,%2,%3};"
        : "+f"(c[0]), "+f"(c[1]), "+f"(c[2]), "+f"(c[3])
        : "r"(a[0]), "r"(a[1]), "r"(a[2]), "r"(a[3]), "r"(b[0]), "r"(b[1]));
}

__device__ __forceinline__ unsigned a_frag_off(int mrow0, int mf, int lane, int ks) {
    return 2u * ((unsigned)(mrow0 + mf * 16 + (lane & 15)) * 136u
                 + (unsigned)((lane >> 4) * 8) + (unsigned)ks * 16u);
}
__device__ __forceinline__ unsigned b_frag_off(int ncol0, int nf, int lane, int ks) {
    return 2u * ((unsigned)(ncol0 + nf * 8 + (lane & 7)) * 136u
                 + (unsigned)(((lane >> 3) & 1) * 8) + (unsigned)ks * 16u);
}

// 3-term: (Ah+Al)·Bh + Ah·Bl   (featM)
__device__ __forceinline__ void mma_tile3(float acc[4][4][4], unsigned aAh, unsigned aAl,
                                          unsigned aBh, unsigned aBl, int lane,
                                          int warp_m, int warp_n) {
    int mrow0 = warp_m * 64, ncol0 = warp_n * 32;
    #pragma unroll
    for (int ks = 0; ks < 8; ks++) {
        unsigned ah[4][4], al[4][4], bh[4][2], bl[4][2];
        #pragma unroll
        for (int mf = 0; mf < 4; mf++) {
            unsigned off = a_frag_off(mrow0, mf, lane, ks);
            LDSM4(ah[mf], aAh + off);
            LDSM4(al[mf], aAl + off);
        }
        #pragma unroll
        for (int nf = 0; nf < 4; nf++) {
            unsigned off = b_frag_off(ncol0, nf, lane, ks);
            LDSM2(bh[nf], aBh + off);
            LDSM2(bl[nf], aBl + off);
        }
        #pragma unroll
        for (int mf = 0; mf < 4; mf++)
            #pragma unroll
            for (int nf = 0; nf < 4; nf++) {
                mma_f16(acc[mf][nf], ah[mf], bh[nf]);
                mma_f16(acc[mf][nf], al[mf], bh[nf]);
                mma_f16(acc[mf][nf], ah[mf], bl[nf]);
            }
    }
}

// 2-term A-split: (Ah+Al)·Bh   (gemm2)
__device__ __forceinline__ void mma_tile2A(float acc[4][4][4], unsigned aAh, unsigned aAl,
                                           unsigned aBh, int lane, int warp_m, int warp_n) {
    int mrow0 = warp_m * 64, ncol0 = warp_n * 32;
    #pragma unroll
    for (int ks = 0; ks < 8; ks++) {
        unsigned ah[4][4], al[4][4], bh[4][2];
        #pragma unroll
        for (int mf = 0; mf < 4; mf++) {
            unsigned off = a_frag_off(mrow0, mf, lane, ks);
            LDSM4(ah[mf], aAh + off);
            LDSM4(al[mf], aAl + off);
        }
        #pragma unroll
        for (int nf = 0; nf < 4; nf++)
            LDSM2(bh[nf], aBh + b_frag_off(ncol0, nf, lane, ks));
        #pragma unroll
        for (int mf = 0; mf < 4; mf++)
            #pragma unroll
            for (int nf = 0; nf < 4; nf++) {
                mma_f16(acc[mf][nf], ah[mf], bh[nf]);
                mma_f16(acc[mf][nf], al[mf], bh[nf]);
            }
    }
}

// 2-term B-split: Ah·(Bh+Bl)   (gemm3)
__device__ __forceinline__ void mma_tile2B(float acc[4][4][4], unsigned aAh,
                                           unsigned aBh, unsigned aBl, int lane,
                                           int warp_m, int warp_n) {
    int mrow0 = warp_m * 64, ncol0 = warp_n * 32;
    #pragma unroll
    for (int ks = 0; ks < 8; ks++) {
        unsigned ah[4][4], bh[4][2], bl[4][2];
        #pragma unroll
        for (int mf = 0; mf < 4; mf++)
            LDSM4(ah[mf], aAh + a_frag_off(mrow0, mf, lane, ks));
        #pragma unroll
        for (int nf = 0; nf < 4; nf++) {
            unsigned off = b_frag_off(ncol0, nf, lane, ks);
            LDSM2(bh[nf], aBh + off);
            LDSM2(bl[nf], aBl + off);
        }
        #pragma unroll
        for (int mf = 0; mf < 4; mf++)
            #pragma unroll
            for (int nf = 0; nf < 4; nf++) {
                mma_f16(acc[mf][nf], ah[mf], bh[nf]);
                mma_f16(acc[mf][nf], ah[mf], bl[nf]);
            }
    }
}

__device__ __forceinline__ void load_B_tile(__half* Bs, const __half* gB, int tid) {
    for (int i = tid; i < 128 * 16; i += 256) {
        int n = i >> 4, q = i & 15;
        ((uint4*)(Bs + n * 136))[q] = ((const uint4*)(gB + n * 128))[q];
    }
}

// ---------------- merged weight prep + init ----------------
// blockIdx.x: 0 -> W (hi+lo), 1..4 -> W1 nt (hi only), 5..8 -> W2 kc (hi+lo), 9 -> init
__global__ void k_prepAll(const float* __restrict__ W, const float* __restrict__ W1,
                          const float* __restrict__ W2) {
    int t = blockIdx.x;
    if (t == 9) {
        int i = blockIdx.y * blockDim.x + threadIdx.x;
        int stride = 8 * blockDim.x;
        for (int j = i; j < Nn; j += stride) g_deg[j] = 0;
        if (i < Dd) { g_sum1[i] = 0.0; g_sq1[i] = 0.0; g_sum2[i] = 0.0; g_sq2[i] = 0.0; }
        if (i == 0) g_total = 0;
        return;
    }
    const float* src; __half *dh, *dl; int Ncols, kc, nt, KC;
    if (t == 0)      { src = W;  dh = g_Wp_h;  dl = g_Wp_l;  Ncols = Dd;   kc = 0;     nt = 0;     KC = 1; }
    else if (t <= 4) { src = W1; dh = g_W1p_h; dl = 0;       Ncols = HIDd; kc = 0;     nt = t - 1; KC = 1; }
    else             { src = W2; dh = g_W2p_h; dl = g_W2p_l; Ncols = Dd;   kc = t - 5; nt = 0;     KC = 4; }
    size_t tb = ((size_t)nt * KC + kc) * 16384;
    int z0 = blockIdx.y * 2048, z1 = z0 + 2048;
    for (int i = z0 + threadIdx.x; i < z1; i += blockDim.x) {
        int n = i >> 7, k = i & 127;
        float v = src[(size_t)(kc * 128 + k) * Ncols + nt * 128 + n];
        __half h = __float2half(v);
        dh[tb + (size_t)n * 128 + k] = h;
        if (dl) dl[tb + (size_t)n * 128 + k] = __float2half(v - __half2float(h));
    }
}

// ---------------- feat = x @ W (MMA, 3-term) + el/er epilogue ----------------
__global__ void __launch_bounds__(256, 1) k_featM(const float* __restrict__ x,
        const float* __restrict__ attn_l, const float* __restrict__ attn_r) {
    extern __shared__ char sm[];
    __half* As_h = (__half*)sm;
    __half* As_l = (__half*)(sm + OFF_AL);
    __half* Bs_h = (__half*)(sm + OFF_BH);
    __half* Bs_l = (__half*)(sm + OFF_BL);
    unsigned sb = smem_u32(sm);
    int tid = threadIdx.x, wid = tid >> 5, lane = tid & 31;
    int warp_m = wid & 1, warp_n = wid >> 1;
    int g = lane >> 2, tig = lane & 3;
    int r0 = blockIdx.x * 128;

    {
        int row = tid >> 1, cb = (tid & 1) * 64;
        int grow = r0 + row;
        __half* dh = As_h + row * 136 + cb;
        __half* dl = As_l + row * 136 + cb;
        if (grow < Nn) {
            const float* srcrow = x + (size_t)grow * 128 + cb;
            #pragma unroll
            for (int j = 0; j < 16; j++)
                split_store4(dh + j * 4, dl + j * 4, *(const float4*)(srcrow + j * 4));
        } else {
            #pragma unroll
            for (int j = 0; j < 32; j++) {
                ((unsigned*)dh)[j] = 0u; ((unsigned*)dl)[j] = 0u;
            }
        }
    }
    load_B_tile(Bs_h, g_Wp_h, tid);
    load_B_tile(Bs_l, g_Wp_l, tid);
    __syncthreads();

    float acc[4][4][4];
    #pragma unroll
    for (int a = 0; a < 4; a++)
        #pragma unroll
        for (int b = 0; b < 4; b++)
            #pragma unroll
            for (int c = 0; c < 4; c++) acc[a][b][c] = 0.0f;
    mma_tile3(acc, sb, sb + OFF_AL, sb + OFF_BH, sb + OFF_BL, lane, warp_m, warp_n);

    int mrow0 = warp_m * 64, ncol0 = warp_n * 32;
    float attl[4][2], attr[4][2];
    #pragma unroll
    for (int nf = 0; nf < 4; nf++) {
        int col = ncol0 + nf * 8 + tig * 2;
        attl[nf][0] = attn_l[col]; attl[nf][1] = attn_l[col + 1];
        attr[nf][0] = attn_r[col]; attr[nf][1] = attn_r[col + 1];
    }
    float sl[4][2][2], sr[4][2][2];
    #pragma unroll
    for (int mf = 0; mf < 4; mf++)
        #pragma unroll
        for (int rh = 0; rh < 2; rh++)
            #pragma unroll
            for (int h2 = 0; h2 < 2; h2++) { sl[mf][rh][h2] = 0.f; sr[mf][rh][h2] = 0.f; }

    #pragma unroll
    for (int mf = 0; mf < 4; mf++) {
        #pragma unroll
        for (int nf = 0; nf < 4; nf++) {
            int col = ncol0 + nf * 8 + tig * 2;
            int row = r0 + mrow0 + mf * 16 + g;
            float c0 = acc[mf][nf][0], c1 = acc[mf][nf][1];
            float c2 = acc[mf][nf][2], c3 = acc[mf][nf][3];
            if (row < Nn)      *(float2*)&g_feat[(size_t)row * 128 + col] = make_float2(c0, c1);
            if (row + 8 < Nn)  *(float2*)&g_feat[(size_t)(row + 8) * 128 + col] = make_float2(c2, c3);
            int h2 = nf >> 1;
            sl[mf][0][h2] += c0 * attl[nf][0] + c1 * attl[nf][1];
            sl[mf][1][h2] += c2 * attl[nf][0] + c3 * attl[nf][1];
            sr[mf][0][h2] += c0 * attr[nf][0] + c1 * attr[nf][1];
            sr[mf][1][h2] += c2 * attr[nf][0] + c3 * attr[nf][1];
        }
    }
    #pragma unroll
    for (int mf = 0; mf < 4; mf++)
        #pragma unroll
        for (int rh = 0; rh < 2; rh++)
            #pragma unroll
            for (int h2 = 0; h2 < 2; h2++) {
                float vl = sl[mf][rh][h2], vr = sr[mf][rh][h2];
                vl += __shfl_down_sync(0xffffffffu, vl, 1, 4);
                vl += __shfl_down_sync(0xffffffffu, vl, 2, 4);
                vr += __shfl_down_sync(0xffffffffu, vr, 1, 4);
                vr += __shfl_down_sync(0xffffffffu, vr, 2, 4);
                if (tig == 0) {
                    int row = r0 + mrow0 + mf * 16 + g + rh * 8;
                    if (row < Nn) {
                        int h = warp_n * 2 + h2;
                        g_el[row * 8 + h] = vl;
                        g_er[row * 8 + h] = vr;
                    }
                }
            }
}

// ---------------- CSR build ----------------
__global__ void k_hist(const int* __restrict__ dst) {
    int i = blockIdx.x * blockDim.x + threadIdx.x;
    if (i < Ee) atomicAdd(&g_deg[dst[i]], 1);
}

__global__ void __launch_bounds__(1024) k_allocScan() {
    __shared__ int swsum[32];
    __shared__ int sbase;
    int i = blockIdx.x * blockDim.x + threadIdx.x;
    int wid = threadIdx.x >> 5, lane = threadIdx.x & 31;
    int deg = (i < Nn) ? g_deg[i] : 0;
    int v = deg;
    #pragma unroll
    for (int off = 1; off < 32; off <<= 1) {
        int t = __shfl_up_sync(0xffffffffu, v, off);
        if (lane >= off) v += t;
    }
    if (lane == 31) swsum[wid] = v;
    __syncthreads();
    if (wid == 0) {
        int w = swsum[lane];
        int wv = w;
        #pragma unroll
        for (int off = 1; off < 32; off <<= 1) {
            int t = __shfl_up_sync(0xffffffffu, wv, off);
            if (lane >= off) wv += t;
        }
        swsum[lane] = wv - w;
        if (lane == 31) sbase = atomicAdd(&g_total, wv);
    }
    __syncthreads();
    if (i < Nn) {
        int start = sbase + swsum[wid] + (v - deg);
        g_startA[i] = start;
        g_cursor[i] = start;
    }
}

__global__ void k_scatter(const int* __restrict__ src, const int* __restrict__ dst) {
    int i = blockIdx.x * blockDim.x + threadIdx.x;
    if (i >= Ee) return;
    int p = atomicAdd(&g_cursor[dst[i]], 1);
    g_csrc[p] = src[i];
}

// ---------------- fused softmax + aggregate + BN1 stats: warp per dst node ----------------
// grid is exact (50000 = 6250*8): every warp has a valid d, so __syncthreads is safe.
#define ACAP 64
__global__ void __launch_bounds__(256) k_agg(const float* __restrict__ bias) {
    __shared__ int   ssrc[8][ACAP];
    __shared__ float salpha[8][ACAP][8];
    __shared__ float smInv[8][8];
    __shared__ float s_sum[128], s_sq[128];
    int wid = threadIdx.x >> 5, lane = threadIdx.x & 31;
    int tid = threadIdx.x;
    int d = blockIdx.x * 8 + wid;
    float4 b4 = *(const float4*)(bias + lane * 4);
    if (tid < 128) { s_sum[tid] = 0.0f; s_sq[tid] = 0.0f; }
    __syncthreads();

    int start = g_startA[d], deg = g_deg[d];
    float4 er0 = *(const float4*)(g_er + d * 8);
    float4 er1 = *(const float4*)(g_er + d * 8 + 4);

    float ds[8];
    #pragma unroll
    for (int h = 0; h < 8; h++) ds[h] = 0.0f;
    for (int j = lane; j < deg; j += 32) {
        int s = g_csrc[start + j];
        float4 l0 = *(const float4*)(g_el + s * 8);
        float4 l1 = *(const float4*)(g_el + s * 8 + 4);
        float e[8] = { l0.x + er0.x, l0.y + er0.y, l0.z + er0.z, l0.w + er0.w,
                       l1.x + er1.x, l1.y + er1.y, l1.z + er1.z, l1.w + er1.w };
        float ee[8];
        #pragma unroll
        for (int h = 0; h < 8; h++) {
            float v = e[h];
            v = (v > 0.0f) ? v : SLOPEf * v;
            ee[h] = __expf(v);
            ds[h] += ee[h];
        }
        if (j < ACAP) {
            ssrc[wid][j] = s;
            ((float4*)salpha[wid][j])[0] = make_float4(ee[0], ee[1], ee[2], ee[3]);
            ((float4*)salpha[wid][j])[1] = make_float4(ee[4], ee[5], ee[6], ee[7]);
        }
    }
    #pragma unroll
    for (int off = 16; off > 0; off >>= 1)
        #pragma unroll
        for (int h = 0; h < 8; h++)
            ds[h] += __shfl_xor_sync(0xffffffffu, ds[h], off);
    #pragma unroll
    for (int h = 0; h < 8; h++)
        if (lane == h) smInv[wid][h] = (ds[h] > 0.0f) ? (1.0f / ds[h]) : 0.0f;
    __syncwarp();

    int hh = lane >> 2;
    float inv = smInv[wid][hh];
    float ax = 0.f, ay = 0.f, az = 0.f, aw = 0.f;
    int jcap = (deg < ACAP) ? deg : ACAP;
    int j = 0;
    for (; j + 4 <= jcap; j += 4) {
        int s0 = ssrc[wid][j],     s1 = ssrc[wid][j + 1];
        int s2 = ssrc[wid][j + 2], s3 = ssrc[wid][j + 3];
        float a0 = salpha[wid][j][hh]     * inv;
        float a1 = salpha[wid][j + 1][hh] * inv;
        float a2 = salpha[wid][j + 2][hh] * inv;
        float a3 = salpha[wid][j + 3][hh] * inv;
        float4 f0 = *(const float4*)(g_feat + (size_t)s0 * 128 + lane * 4);
        float4 f1 = *(const float4*)(g_feat + (size_t)s1 * 128 + lane * 4);
        float4 f2 = *(const float4*)(g_feat + (size_t)s2 * 128 + lane * 4);
        float4 f3 = *(const float4*)(g_feat + (size_t)s3 * 128 + lane * 4);
        ax += f0.x * a0 + f1.x * a1 + f2.x * a2 + f3.x * a3;
        ay += f0.y * a0 + f1.y * a1 + f2.y * a2 + f3.y * a3;
        az += f0.z * a0 + f1.z * a1 + f2.z * a2 + f3.z * a3;
        aw += f0.w * a0 + f1.w * a1 + f2.w * a2 + f3.w * a3;
    }
    for (; j < jcap; j++) {
        int s0 = ssrc[wid][j];
        float a0 = salpha[wid][j][hh] * inv;
        float4 f0 = *(const float4*)(g_feat + (size_t)s0 * 128 + lane * 4);
        ax += f0.x * a0; ay += f0.y * a0; az += f0.z * a0; aw += f0.w * a0;
    }
    for (; j < deg; j++) {
        int s0 = g_csrc[start + j];
        float erh = g_er[d * 8 + hh];
        float e = g_el[s0 * 8 + hh] + erh;
        e = (e > 0.0f) ? e : SLOPEf * e;
        float a0 = __expf(e) * inv;
        float4 f0 = *(const float4*)(g_feat + (size_t)s0 * 128 + lane * 4);
        ax += f0.x * a0; ay += f0.y * a0; az += f0.z * a0; aw += f0.w * a0;
    }
    float vx = ax + b4.x, vy = ay + b4.y, vz = az + b4.z, vw = aw + b4.w;
    *(float4*)(g_agg + (size_t)d * 128 + lane * 4) = make_float4(vx, vy, vz, vw);

    // BN1 stats: smem column partials then one double-atomic per column per block
    int c0 = lane * 4;
    atomicAdd(&s_sum[c0 + 0], vx); atomicAdd(&s_sq[c0 + 0], vx * vx);
    atomicAdd(&s_sum[c0 + 1], vy); atomicAdd(&s_sq[c0 + 1], vy * vy);
    atomicAdd(&s_sum[c0 + 2], vz); atomicAdd(&s_sq[c0 + 2], vz * vz);
    atomicAdd(&s_sum[c0 + 3], vw); atomicAdd(&s_sq[c0 + 3], vw * vw);
    __syncthreads();
    if (tid < 128) {
        atomicAdd(&g_sum1[tid], (double)s_sum[tid]);
        atomicAdd(&g_sq1[tid], (double)s_sq[tid]);
    }
}

// ---------------- gemm2: hid = relu(BN1(h1) @ W1 + b1), 2-term A-split ----------------
__global__ void __launch_bounds__(256) k_gemm2M(const float* __restrict__ b1,
        const float* __restrict__ bn1g, const float* __restrict__ bn1b) {
    extern __shared__ char sm[];
    __half* As_h = (__half*)sm;
    __half* As_l = (__half*)(sm + G2_AL);
    __half* Bs_h = (__half*)(sm + G2_BH);
    float* ssc = (float*)(sm + G2_SC);
    float* ssh = (float*)(sm + G2_SH);
    unsigned sb = smem_u32(sm);
    int tid = threadIdx.x, wid = tid >> 5, lane = tid & 31;
    int warp_m = wid & 1, warp_n = wid >> 1;
    int g = lane >> 2, tig = lane & 3;
    int r0 = blockIdx.x * 128;

    if (tid < 128) {
        double mu  = g_sum1[tid] / (double)Nn;
        double var = g_sq1[tid] / (double)Nn - mu * mu;
        double sc  = (double)bn1g[tid] * rsqrt(var + (double)EPSf);
        ssc[tid] = (float)sc;
        ssh[tid] = (float)((double)bn1b[tid] - mu * sc);
    }
    __syncthreads();

    {
        int row = tid >> 1, cb = (tid & 1) * 64;
        int grow = r0 + row;
        __half* dh = As_h + row * 136 + cb;
        __half* dl = As_l + row * 136 + cb;
        if (grow < Nn) {
            const float* srcrow = g_agg + (size_t)grow * 128 + cb;
            #pragma unroll
            for (int j = 0; j < 16; j++) {
                float4 v = *(const float4*)(srcrow + j * 4);
                int k = cb + j * 4;
                v.x = fmaf(v.x, ssc[k],     ssh[k]);
                v.y = fmaf(v.y, ssc[k + 1], ssh[k + 1]);
                v.z = fmaf(v.z, ssc[k + 2], ssh[k + 2]);
                v.w = fmaf(v.w, ssc[k + 3], ssh[k + 3]);
                split_store4(dh + j * 4, dl + j * 4, v);
            }
        } else {
            #pragma unroll
            for (int j = 0; j < 32; j++) {
                ((unsigned*)dh)[j] = 0u; ((unsigned*)dl)[j] = 0u;
            }
        }
    }

    int mrow0 = warp_m * 64, ncol0 = warp_n * 32;
    for (int nt = 0; nt < 4; nt++) {
        __syncthreads();
        load_B_tile(Bs_h, g_W1p_h + (size_t)nt * 16384, tid);
        __syncthreads();

        float acc[4][4][4];
        #pragma unroll
        for (int a = 0; a < 4; a++)
            #pragma unroll
            for (int b = 0; b < 4; b++)
                #pragma unroll
                for (int c = 0; c < 4; c++) acc[a][b][c] = 0.0f;
        mma_tile2A(acc, sb, sb + G2_AL, sb + G2_BH, lane, warp_m, warp_n);

        #pragma unroll
        for (int nf = 0; nf < 4; nf++) {
            int colg = nt * 128 + ncol0 + nf * 8 + tig * 2;
            float bb0 = b1[colg], bb1 = b1[colg + 1];
            #pragma unroll
            for (int mf = 0; mf < 4; mf++) {
                int row = r0 + mrow0 + mf * 16 + g;
                float v0 = acc[mf][nf][0] + bb0; v0 = (v0 > 0.f) ? v0 : 0.f;
                float v1 = acc[mf][nf][1] + bb1; v1 = (v1 > 0.f) ? v1 : 0.f;
                float v2 = acc[mf][nf][2] + bb0; v2 = (v2 > 0.f) ? v2 : 0.f;
                float v3 = acc[mf][nf][3] + bb1; v3 = (v3 > 0.f) ? v3 : 0.f;
                if (row < Nn)
                    *(__half2*)&g_hid_h[(size_t)row * 512 + colg] = __floats2half2_rn(v0, v1);
                if (row + 8 < Nn)
                    *(__half2*)&g_hid_h[(size_t)(row + 8) * 512 + colg] = __floats2half2_rn(v2, v3);
            }
        }
    }
}

// ---------------- gemm3: h2 = hid @ W2 + b2, 2-term B-split + fused BN2 stats ----------------
__global__ void __launch_bounds__(256) k_gemm3M(const float* __restrict__ b2) {
    extern __shared__ char sm[];
    __half* As_h = (__half*)sm;
    __half* Bs_h = (__half*)(sm + G3_BH);
    __half* Bs_l = (__half*)(sm + G3_BL);
    float* s_sum = (float*)(sm + G3_ST);
    float* s_sq  = (float*)(sm + G3_ST + 512);
    unsigned sb = smem_u32(sm);
    int tid = threadIdx.x, wid = tid >> 5, lane = tid & 31;
    int warp_m = wid & 1, warp_n = wid >> 1;
    int g = lane >> 2, tig = lane & 3;
    int r0 = blockIdx.x * 128;

    if (tid < 128) { s_sum[tid] = 0.0f; s_sq[tid] = 0.0f; }

    float acc[4][4][4];
    #pragma unroll
    for (int a = 0; a < 4; a++)
        #pragma unroll
        for (int b = 0; b < 4; b++)
            #pragma unroll
            for (int c = 0; c < 4; c++) acc[a][b][c] = 0.0f;

    for (int kc = 0; kc < 4; kc++) {
        __syncthreads();
        {
            int row = tid >> 1, cb = (tid & 1) * 64;
            int grow = r0 + row;
            uint4* dh = (uint4*)(As_h + row * 136 + cb);
            if (grow < Nn) {
                const uint4* shp = (const uint4*)(g_hid_h + (size_t)grow * 512 + kc * 128 + cb);
                #pragma unroll
                for (int j = 0; j < 8; j++) dh[j] = shp[j];
            } else {
                uint4 z = make_uint4(0, 0, 0, 0);
                #pragma unroll
                for (int j = 0; j < 8; j++) dh[j] = z;
            }
        }
        load_B_tile(Bs_h, g_W2p_h + (size_t)kc * 16384, tid);
        load_B_tile(Bs_l, g_W2p_l + (size_t)kc * 16384, tid);
        __syncthreads();
        mma_tile2B(acc, sb, sb + G3_BH, sb + G3_BL, lane, warp_m, warp_n);
    }

    int mrow0 = warp_m * 64, ncol0 = warp_n * 32;
    #pragma unroll
    for (int nf = 0; nf < 4; nf++) {
        int col = ncol0 + nf * 8 + tig * 2;
        float bb0 = b2[col], bb1 = b2[col + 1];
        float cs0 = 0.f, cq0 = 0.f, cs1 = 0.f, cq1 = 0.f;
        #pragma unroll
        for (int mf = 0; mf < 4; mf++) {
            int row = r0 + mrow0 + mf * 16 + g;
            float v0 = acc[mf][nf][0] + bb0, v1 = acc[mf][nf][1] + bb1;
            float v2 = acc[mf][nf][2] + bb0, v3 = acc[mf][nf][3] + bb1;
            if (row < Nn) {
                *(float2*)&g_h2[(size_t)row * 128 + col] = make_float2(v0, v1);
                cs0 += v0; cq0 += v0 * v0; cs1 += v1; cq1 += v1 * v1;
            }
            if (row + 8 < Nn) {
                *(float2*)&g_h2[(size_t)(row + 8) * 128 + col] = make_float2(v2, v3);
                cs0 += v2; cq0 += v2 * v2; cs1 += v3; cq1 += v3 * v3;
            }
        }
        atomicAdd(&s_sum[col], cs0);     atomicAdd(&s_sq[col], cq0);
        atomicAdd(&s_sum[col + 1], cs1); atomicAdd(&s_sq[col + 1], cq1);
    }
    __syncthreads();
    if (tid < 128) {
        atomicAdd(&g_sum2[tid], (double)s_sum[tid]);
        atomicAdd(&g_sq2[tid], (double)s_sq[tid]);
    }
}

// ---------------- out = BN2(h2) ----------------
__global__ void k_out(float* __restrict__ out,
        const float* __restrict__ bn2g, const float* __restrict__ bn2b) {
    __shared__ float s_sc[128], s_sh[128];
    int t = threadIdx.x;
    if (t < 128) {
        double mu  = g_sum2[t] / (double)Nn;
        double var = g_sq2[t] / (double)Nn - mu * mu;
        double sc  = (double)bn2g[t] * rsqrt(var + (double)EPSf);
        s_sc[t] = (float)sc;
        s_sh[t] = (float)((double)bn2b[t] - mu * sc);
    }
    __syncthreads();
    int i = blockIdx.x * blockDim.x + t;
    int total = Nn * Dd / 4;
    int stride = gridDim.x * blockDim.x;
    for (; i < total; i += stride) {
        int c4 = (i & 31) * 4;
        float4 v  = ((const float4*)g_h2)[i];
        float4 sc = *(const float4*)(s_sc + c4);
        float4 sh = *(const float4*)(s_sh + c4);
        v.x = v.x * sc.x + sh.x;
        v.y = v.y * sc.y + sh.y;
        v.z = v.z * sc.z + sh.z;
        v.w = v.w * sc.w + sh.w;
        ((float4*)out)[i] = v;
    }
}

// ---------------- launch ----------------
extern "C" void kernel_launch(void* const* d_in, const int* in_sizes, int n_in,
                              void* d_out, int out_size) {
    const float* x        = (const float*)d_in[0];
    const int*   src      = (const int*)d_in[1];
    const int*   dst      = (const int*)d_in[2];
    const float* W        = (const float*)d_in[3];
    const float* attn_l   = (const float*)d_in[4];
    const float* attn_r   = (const float*)d_in[5];
    const float* bias_gat = (const float*)d_in[6];
    const float* bn1g     = (const float*)d_in[7];
    const float* bn1b     = (const float*)d_in[8];
    const float* W1       = (const float*)d_in[9];
    const float* b1       = (const float*)d_in[10];
    const float* W2       = (const float*)d_in[11];
    const float* b2       = (const float*)d_in[12];
    const float* bn2g     = (const float*)d_in[13];
    const float* bn2b     = (const float*)d_in[14];
    float* out = (float*)d_out;

    static int configured = 0;
    if (!configured) {
        cudaFuncSetAttribute(k_featM,  cudaFuncAttributeMaxDynamicSharedMemorySize, SM_FEAT);
        cudaFuncSetAttribute(k_gemm2M, cudaFuncAttributeMaxDynamicSharedMemorySize, SM_G2);
        cudaFuncSetAttribute(k_gemm3M, cudaFuncAttributeMaxDynamicSharedMemorySize, SM_G3);
        configured = 1;
    }

    k_prepAll<<<dim3(10, 8), 256>>>(W, W1, W2);
    k_hist<<<(Ee + 255) / 256, 256>>>(dst);
    k_allocScan<<<(Nn + 1023) / 1024, 1024>>>();
    k_scatter<<<(Ee + 255) / 256, 256>>>(src, dst);
    k_featM<<<MT, 256, SM_FEAT>>>(x, attn_l, attn_r);
    k_agg<<<Nn / 8, 256>>>(bias_gat);
    k_gemm2M<<<MT, 256, SM_G2>>>(b1, bn1g, bn1b);
    k_gemm3M<<<MT, 256, SM_G3>>>(b2);
    k_out<<<2048, 256>>>(out, bn2g, bn2b);
}

// round 14
// speedup vs baseline: 1.0605x; 1.0605x over previous
#include <cuda_runtime.h>
#include <cuda_fp16.h>
#include <cuda_bf16.h>

// Problem constants
#define Nn   50000
#define Ee   800000
#define Dd   128
#define Hh   8
#define HIDd 512
#define SLOPEf 0.2f
#define EPSf 1e-5f
#define MT   391          // ceil(50000/128) row tiles

// featM smem layout (3-term: Ah Al Bh Bl)
#define OFF_AL 34816
#define OFF_BH 69632
#define OFF_BL 104448
#define SM_FEAT 139264
// gemm2 smem layout (Ah Al Bh + BN consts)
#define G2_AL 34816
#define G2_BH 69632
#define G2_SC 104448
#define G2_SH 104960
#define SM_G2 105472
// gemm3 smem layout (Ah Bh Bl + stats)
#define G3_BH 34816
#define G3_BL 69632
#define G3_ST 104448
#define SM_G3 105472

// ---------------- device scratch ----------------
__device__ __align__(16) float    g_feat[Nn * Dd];
__device__ __align__(16) float    g_el[Nn * Hh];
__device__ __align__(16) float    g_er[Nn * Hh];
__device__ __align__(16) float    g_agg[Nn * Dd];
__device__ __align__(16) float    g_h2[Nn * Dd];
// CSR
__device__ int g_deg[Nn];
__device__ int g_startA[Nn];
__device__ int g_cursor[Nn];
__device__ int g_csrc[Ee];
__device__ int g_total;
// prepared fp16-split weights, [tile][n][k] k-contiguous
__device__ __align__(16) __half g_Wp_h[Dd * Dd],    g_Wp_l[Dd * Dd];
__device__ __align__(16) __half g_W1p_h[Dd * HIDd];
__device__ __align__(16) __half g_W2p_h[HIDd * Dd], g_W2p_l[HIDd * Dd];
// hidden activations, fp16 hi plane only, [row][512]
__device__ __align__(16) __half g_hid_h[(size_t)Nn * HIDd];
__device__ double g_sum1[Dd], g_sq1[Dd], g_sum2[Dd], g_sq2[Dd];

// ---------------- small helpers ----------------
__device__ __forceinline__ unsigned smem_u32(const void* p) {
    unsigned a;
    asm("{ .reg .u64 t; cvta.to.shared.u64 t, %1; cvt.u32.u64 %0, t; }" : "=r"(a) : "l"(p));
    return a;
}
__device__ __forceinline__ void split_store4(__half* dh, __half* dl, float4 v) {
    __half2 h0 = __floats2half2_rn(v.x, v.y);
    __half2 h1 = __floats2half2_rn(v.z, v.w);
    float2 f0 = __half22float2(h0);
    float2 f1 = __half22float2(h1);
    __half2 l0 = __floats2half2_rn(v.x - f0.x, v.y - f0.y);
    __half2 l1 = __floats2half2_rn(v.z - f1.x, v.w - f1.y);
    *(__half2*)(dh)     = h0;  *(__half2*)(dh + 2) = h1;
    *(__half2*)(dl)     = l0;  *(__half2*)(dl + 2) = l1;
}

// ---------------- mma.sync primitives ----------------
#define LDSM4(r, a) asm volatile("ldmatrix.sync.aligned.m8n8.x4.shared.b16 {%0,%1,%2,%3}, [%4];" \
    : "=r"((r)[0]), "=r"((r)[1]), "=r"((r)[2]), "=r"((r)[3]) : "r"(a))
#define LDSM2(r, a) asm volatile("ldmatrix.sync.aligned.m8n8.x2.shared.b16 {%0,%1}, [%2];" \
    : "=r"((r)[0]), "=r"((r)[1]) : "r"(a))

__device__ __forceinline__ void mma_f16(float c[4], const unsigned a[4], const unsigned b[2]) {
    asm volatile("mma.sync.aligned.m16n8k16.row.col.f32.f16.f16.f32 "
        "{%0,%1,%2,%3}, {%4,%5,%6,%7}, {%8,%9}, {%0,%1,%2,%3};"
        : "+f"(c[0]), "+f"(c[1]), "+f"(c[2]), "+f"(c[3])
        : "r"(a[0]), "r"(a[1]), "r"(a[2]), "r"(a[3]), "r"(b[0]), "r"(b[1]));
}

__device__ __forceinline__ unsigned a_frag_off(int mrow0, int mf, int lane, int ks) {
    return 2u * ((unsigned)(mrow0 + mf * 16 + (lane & 15)) * 136u
                 + (unsigned)((lane >> 4) * 8) + (unsigned)ks * 16u);
}
__device__ __forceinline__ unsigned b_frag_off(int ncol0, int nf, int lane, int ks) {
    return 2u * ((unsigned)(ncol0 + nf * 8 + (lane & 7)) * 136u
                 + (unsigned)(((lane >> 3) & 1) * 8) + (unsigned)ks * 16u);
}

// 3-term: (Ah+Al)·Bh + Ah·Bl   (featM)
__device__ __forceinline__ void mma_tile3(float acc[4][4][4], unsigned aAh, unsigned aAl,
                                          unsigned aBh, unsigned aBl, int lane,
                                          int warp_m, int warp_n) {
    int mrow0 = warp_m * 64, ncol0 = warp_n * 32;
    #pragma unroll
    for (int ks = 0; ks < 8; ks++) {
        unsigned ah[4][4], al[4][4], bh[4][2], bl[4][2];
        #pragma unroll
        for (int mf = 0; mf < 4; mf++) {
            unsigned off = a_frag_off(mrow0, mf, lane, ks);
            LDSM4(ah[mf], aAh + off);
            LDSM4(al[mf], aAl + off);
        }
        #pragma unroll
        for (int nf = 0; nf < 4; nf++) {
            unsigned off = b_frag_off(ncol0, nf, lane, ks);
            LDSM2(bh[nf], aBh + off);
            LDSM2(bl[nf], aBl + off);
        }
        #pragma unroll
        for (int mf = 0; mf < 4; mf++)
            #pragma unroll
            for (int nf = 0; nf < 4; nf++) {
                mma_f16(acc[mf][nf], ah[mf], bh[nf]);
                mma_f16(acc[mf][nf], al[mf], bh[nf]);
                mma_f16(acc[mf][nf], ah[mf], bl[nf]);
            }
    }
}

// 2-term A-split: (Ah+Al)·Bh   (gemm2)
__device__ __forceinline__ void mma_tile2A(float acc[4][4][4], unsigned aAh, unsigned aAl,
                                           unsigned aBh, int lane, int warp_m, int warp_n) {
    int mrow0 = warp_m * 64, ncol0 = warp_n * 32;
    #pragma unroll
    for (int ks = 0; ks < 8; ks++) {
        unsigned ah[4][4], al[4][4], bh[4][2];
        #pragma unroll
        for (int mf = 0; mf < 4; mf++) {
            unsigned off = a_frag_off(mrow0, mf, lane, ks);
            LDSM4(ah[mf], aAh + off);
            LDSM4(al[mf], aAl + off);
        }
        #pragma unroll
        for (int nf = 0; nf < 4; nf++)
            LDSM2(bh[nf], aBh + b_frag_off(ncol0, nf, lane, ks));
        #pragma unroll
        for (int mf = 0; mf < 4; mf++)
            #pragma unroll
            for (int nf = 0; nf < 4; nf++) {
                mma_f16(acc[mf][nf], ah[mf], bh[nf]);
                mma_f16(acc[mf][nf], al[mf], bh[nf]);
            }
    }
}

// 2-term B-split: Ah·(Bh+Bl)   (gemm3)
__device__ __forceinline__ void mma_tile2B(float acc[4][4][4], unsigned aAh,
                                           unsigned aBh, unsigned aBl, int lane,
                                           int warp_m, int warp_n) {
    int mrow0 = warp_m * 64, ncol0 = warp_n * 32;
    #pragma unroll
    for (int ks = 0; ks < 8; ks++) {
        unsigned ah[4][4], bh[4][2], bl[4][2];
        #pragma unroll
        for (int mf = 0; mf < 4; mf++)
            LDSM4(ah[mf], aAh + a_frag_off(mrow0, mf, lane, ks));
        #pragma unroll
        for (int nf = 0; nf < 4; nf++) {
            unsigned off = b_frag_off(ncol0, nf, lane, ks);
            LDSM2(bh[nf], aBh + off);
            LDSM2(bl[nf], aBl + off);
        }
        #pragma unroll
        for (int mf = 0; mf < 4; mf++)
            #pragma unroll
            for (int nf = 0; nf < 4; nf++) {
                mma_f16(acc[mf][nf], ah[mf], bh[nf]);
                mma_f16(acc[mf][nf], ah[mf], bl[nf]);
            }
    }
}

__device__ __forceinline__ void load_B_tile(__half* Bs, const __half* gB, int tid) {
    for (int i = tid; i < 128 * 16; i += 256) {
        int n = i >> 4, q = i & 15;
        ((uint4*)(Bs + n * 136))[q] = ((const uint4*)(gB + n * 128))[q];
    }
}

// ---------------- merged weight prep + init ----------------
// blockIdx.x: 0 -> W (hi+lo), 1..4 -> W1 nt (hi only), 5..8 -> W2 kc (hi+lo), 9 -> init
__global__ void k_prepAll(const float* __restrict__ W, const float* __restrict__ W1,
                          const float* __restrict__ W2) {
    int t = blockIdx.x;
    if (t == 9) {
        int i = blockIdx.y * blockDim.x + threadIdx.x;
        int stride = 8 * blockDim.x;
        for (int j = i; j < Nn; j += stride) g_deg[j] = 0;
        if (i < Dd) { g_sum1[i] = 0.0; g_sq1[i] = 0.0; g_sum2[i] = 0.0; g_sq2[i] = 0.0; }
        if (i == 0) g_total = 0;
        return;
    }
    const float* src; __half *dh, *dl; int Ncols, kc, nt, KC;
    if (t == 0)      { src = W;  dh = g_Wp_h;  dl = g_Wp_l;  Ncols = Dd;   kc = 0;     nt = 0;     KC = 1; }
    else if (t <= 4) { src = W1; dh = g_W1p_h; dl = 0;       Ncols = HIDd; kc = 0;     nt = t - 1; KC = 1; }
    else             { src = W2; dh = g_W2p_h; dl = g_W2p_l; Ncols = Dd;   kc = t - 5; nt = 0;     KC = 4; }
    size_t tb = ((size_t)nt * KC + kc) * 16384;
    int z0 = blockIdx.y * 2048, z1 = z0 + 2048;
    for (int i = z0 + threadIdx.x; i < z1; i += blockDim.x) {
        int n = i >> 7, k = i & 127;
        float v = src[(size_t)(kc * 128 + k) * Ncols + nt * 128 + n];
        __half h = __float2half(v);
        dh[tb + (size_t)n * 128 + k] = h;
        if (dl) dl[tb + (size_t)n * 128 + k] = __float2half(v - __half2float(h));
    }
}

// ---------------- feat = x @ W (MMA, 3-term) + el/er epilogue ----------------
__global__ void __launch_bounds__(256, 1) k_featM(const float* __restrict__ x,
        const float* __restrict__ attn_l, const float* __restrict__ attn_r) {
    extern __shared__ char sm[];
    __half* As_h = (__half*)sm;
    __half* As_l = (__half*)(sm + OFF_AL);
    __half* Bs_h = (__half*)(sm + OFF_BH);
    __half* Bs_l = (__half*)(sm + OFF_BL);
    unsigned sb = smem_u32(sm);
    int tid = threadIdx.x, wid = tid >> 5, lane = tid & 31;
    int warp_m = wid & 1, warp_n = wid >> 1;
    int g = lane >> 2, tig = lane & 3;
    int r0 = blockIdx.x * 128;

    {
        int row = tid >> 1, cb = (tid & 1) * 64;
        int grow = r0 + row;
        __half* dh = As_h + row * 136 + cb;
        __half* dl = As_l + row * 136 + cb;
        if (grow < Nn) {
            const float* srcrow = x + (size_t)grow * 128 + cb;
            #pragma unroll
            for (int j = 0; j < 16; j++)
                split_store4(dh + j * 4, dl + j * 4, *(const float4*)(srcrow + j * 4));
        } else {
            #pragma unroll
            for (int j = 0; j < 32; j++) {
                ((unsigned*)dh)[j] = 0u; ((unsigned*)dl)[j] = 0u;
            }
        }
    }
    load_B_tile(Bs_h, g_Wp_h, tid);
    load_B_tile(Bs_l, g_Wp_l, tid);
    __syncthreads();

    float acc[4][4][4];
    #pragma unroll
    for (int a = 0; a < 4; a++)
        #pragma unroll
        for (int b = 0; b < 4; b++)
            #pragma unroll
            for (int c = 0; c < 4; c++) acc[a][b][c] = 0.0f;
    mma_tile3(acc, sb, sb + OFF_AL, sb + OFF_BH, sb + OFF_BL, lane, warp_m, warp_n);

    int mrow0 = warp_m * 64, ncol0 = warp_n * 32;
    float attl[4][2], attr[4][2];
    #pragma unroll
    for (int nf = 0; nf < 4; nf++) {
        int col = ncol0 + nf * 8 + tig * 2;
        attl[nf][0] = attn_l[col]; attl[nf][1] = attn_l[col + 1];
        attr[nf][0] = attn_r[col]; attr[nf][1] = attn_r[col + 1];
    }
    float sl[4][2][2], sr[4][2][2];
    #pragma unroll
    for (int mf = 0; mf < 4; mf++)
        #pragma unroll
        for (int rh = 0; rh < 2; rh++)
            #pragma unroll
            for (int h2 = 0; h2 < 2; h2++) { sl[mf][rh][h2] = 0.f; sr[mf][rh][h2] = 0.f; }

    #pragma unroll
    for (int mf = 0; mf < 4; mf++) {
        #pragma unroll
        for (int nf = 0; nf < 4; nf++) {
            int col = ncol0 + nf * 8 + tig * 2;
            int row = r0 + mrow0 + mf * 16 + g;
            float c0 = acc[mf][nf][0], c1 = acc[mf][nf][1];
            float c2 = acc[mf][nf][2], c3 = acc[mf][nf][3];
            if (row < Nn)      *(float2*)&g_feat[(size_t)row * 128 + col] = make_float2(c0, c1);
            if (row + 8 < Nn)  *(float2*)&g_feat[(size_t)(row + 8) * 128 + col] = make_float2(c2, c3);
            int h2 = nf >> 1;
            sl[mf][0][h2] += c0 * attl[nf][0] + c1 * attl[nf][1];
            sl[mf][1][h2] += c2 * attl[nf][0] + c3 * attl[nf][1];
            sr[mf][0][h2] += c0 * attr[nf][0] + c1 * attr[nf][1];
            sr[mf][1][h2] += c2 * attr[nf][0] + c3 * attr[nf][1];
        }
    }
    #pragma unroll
    for (int mf = 0; mf < 4; mf++)
        #pragma unroll
        for (int rh = 0; rh < 2; rh++)
            #pragma unroll
            for (int h2 = 0; h2 < 2; h2++) {
                float vl = sl[mf][rh][h2], vr = sr[mf][rh][h2];
                vl += __shfl_down_sync(0xffffffffu, vl, 1, 4);
                vl += __shfl_down_sync(0xffffffffu, vl, 2, 4);
                vr += __shfl_down_sync(0xffffffffu, vr, 1, 4);
                vr += __shfl_down_sync(0xffffffffu, vr, 2, 4);
                if (tig == 0) {
                    int row = r0 + mrow0 + mf * 16 + g + rh * 8;
                    if (row < Nn) {
                        int h = warp_n * 2 + h2;
                        g_el[row * 8 + h] = vl;
                        g_er[row * 8 + h] = vr;
                    }
                }
            }
}

// ---------------- CSR build ----------------
__global__ void k_hist(const int* __restrict__ dst) {
    int i = blockIdx.x * blockDim.x + threadIdx.x;
    if (i < Ee) atomicAdd(&g_deg[dst[i]], 1);
}

__global__ void __launch_bounds__(1024) k_allocScan() {
    __shared__ int swsum[32];
    __shared__ int sbase;
    int i = blockIdx.x * blockDim.x + threadIdx.x;
    int wid = threadIdx.x >> 5, lane = threadIdx.x & 31;
    int deg = (i < Nn) ? g_deg[i] : 0;
    int v = deg;
    #pragma unroll
    for (int off = 1; off < 32; off <<= 1) {
        int t = __shfl_up_sync(0xffffffffu, v, off);
        if (lane >= off) v += t;
    }
    if (lane == 31) swsum[wid] = v;
    __syncthreads();
    if (wid == 0) {
        int w = swsum[lane];
        int wv = w;
        #pragma unroll
        for (int off = 1; off < 32; off <<= 1) {
            int t = __shfl_up_sync(0xffffffffu, wv, off);
            if (lane >= off) wv += t;
        }
        swsum[lane] = wv - w;
        if (lane == 31) sbase = atomicAdd(&g_total, wv);
    }
    __syncthreads();
    if (i < Nn) {
        int start = sbase + swsum[wid] + (v - deg);
        g_startA[i] = start;
        g_cursor[i] = start;
    }
}

__global__ void k_scatter(const int* __restrict__ src, const int* __restrict__ dst) {
    int i = blockIdx.x * blockDim.x + threadIdx.x;
    if (i >= Ee) return;
    int p = atomicAdd(&g_cursor[dst[i]], 1);
    g_csrc[p] = src[i];
}

// ---------------- fused softmax + aggregate: warp per dst node (barrier-free) ----------------
#define ACAP 64
__global__ void __launch_bounds__(256) k_agg(const float* __restrict__ bias) {
    __shared__ int   ssrc[8][ACAP];
    __shared__ float salpha[8][ACAP][8];
    __shared__ float smInv[8][8];
    int wid = threadIdx.x >> 5, lane = threadIdx.x & 31;
    int d = blockIdx.x * 8 + wid;
    if (d >= Nn) return;
    float4 b4 = *(const float4*)(bias + lane * 4);

    int start = g_startA[d], deg = g_deg[d];
    float4 er0 = *(const float4*)(g_er + d * 8);
    float4 er1 = *(const float4*)(g_er + d * 8 + 4);

    float ds[8];
    #pragma unroll
    for (int h = 0; h < 8; h++) ds[h] = 0.0f;
    for (int j = lane; j < deg; j += 32) {
        int s = g_csrc[start + j];
        float4 l0 = *(const float4*)(g_el + s * 8);
        float4 l1 = *(const float4*)(g_el + s * 8 + 4);
        float e[8] = { l0.x + er0.x, l0.y + er0.y, l0.z + er0.z, l0.w + er0.w,
                       l1.x + er1.x, l1.y + er1.y, l1.z + er1.z, l1.w + er1.w };
        float ee[8];
        #pragma unroll
        for (int h = 0; h < 8; h++) {
            float v = e[h];
            v = (v > 0.0f) ? v : SLOPEf * v;
            ee[h] = __expf(v);
            ds[h] += ee[h];
        }
        if (j < ACAP) {
            ssrc[wid][j] = s;
            ((float4*)salpha[wid][j])[0] = make_float4(ee[0], ee[1], ee[2], ee[3]);
            ((float4*)salpha[wid][j])[1] = make_float4(ee[4], ee[5], ee[6], ee[7]);
        }
    }
    #pragma unroll
    for (int off = 16; off > 0; off >>= 1)
        #pragma unroll
        for (int h = 0; h < 8; h++)
            ds[h] += __shfl_xor_sync(0xffffffffu, ds[h], off);
    #pragma unroll
    for (int h = 0; h < 8; h++)
        if (lane == h) smInv[wid][h] = (ds[h] > 0.0f) ? (1.0f / ds[h]) : 0.0f;
    __syncwarp();

    int hh = lane >> 2;
    float inv = smInv[wid][hh];
    float ax = 0.f, ay = 0.f, az = 0.f, aw = 0.f;
    int jcap = (deg < ACAP) ? deg : ACAP;
    int j = 0;
    for (; j + 4 <= jcap; j += 4) {
        int s0 = ssrc[wid][j],     s1 = ssrc[wid][j + 1];
        int s2 = ssrc[wid][j + 2], s3 = ssrc[wid][j + 3];
        float a0 = salpha[wid][j][hh]     * inv;
        float a1 = salpha[wid][j + 1][hh] * inv;
        float a2 = salpha[wid][j + 2][hh] * inv;
        float a3 = salpha[wid][j + 3][hh] * inv;
        float4 f0 = *(const float4*)(g_feat + (size_t)s0 * 128 + lane * 4);
        float4 f1 = *(const float4*)(g_feat + (size_t)s1 * 128 + lane * 4);
        float4 f2 = *(const float4*)(g_feat + (size_t)s2 * 128 + lane * 4);
        float4 f3 = *(const float4*)(g_feat + (size_t)s3 * 128 + lane * 4);
        ax += f0.x * a0 + f1.x * a1 + f2.x * a2 + f3.x * a3;
        ay += f0.y * a0 + f1.y * a1 + f2.y * a2 + f3.y * a3;
        az += f0.z * a0 + f1.z * a1 + f2.z * a2 + f3.z * a3;
        aw += f0.w * a0 + f1.w * a1 + f2.w * a2 + f3.w * a3;
    }
    for (; j < jcap; j++) {
        int s0 = ssrc[wid][j];
        float a0 = salpha[wid][j][hh] * inv;
        float4 f0 = *(const float4*)(g_feat + (size_t)s0 * 128 + lane * 4);
        ax += f0.x * a0; ay += f0.y * a0; az += f0.z * a0; aw += f0.w * a0;
    }
    for (; j < deg; j++) {
        int s0 = g_csrc[start + j];
        float erh = g_er[d * 8 + hh];
        float e = g_el[s0 * 8 + hh] + erh;
        e = (e > 0.0f) ? e : SLOPEf * e;
        float a0 = __expf(e) * inv;
        float4 f0 = *(const float4*)(g_feat + (size_t)s0 * 128 + lane * 4);
        ax += f0.x * a0; ay += f0.y * a0; az += f0.z * a0; aw += f0.w * a0;
    }
    *(float4*)(g_agg + (size_t)d * 128 + lane * 4) =
        make_float4(ax + b4.x, ay + b4.y, az + b4.z, aw + b4.w);
}

// ---------------- BN1 stats (standalone) ----------------
__global__ void k_stats1() {
    int c = threadIdx.x;
    double s = 0.0, s2 = 0.0;
    for (int r = blockIdx.x; r < Nn; r += gridDim.x) {
        float v = g_agg[(size_t)r * Dd + c];
        s += v; s2 += (double)v * v;
    }
    atomicAdd(&g_sum1[c], s);
    atomicAdd(&g_sq1[c], s2);
}

// ---------------- gemm2: hid = relu(BN1(h1) @ W1 + b1), 2-term A-split ----------------
__global__ void __launch_bounds__(256) k_gemm2M(const float* __restrict__ b1,
        const float* __restrict__ bn1g, const float* __restrict__ bn1b) {
    extern __shared__ char sm[];
    __half* As_h = (__half*)sm;
    __half* As_l = (__half*)(sm + G2_AL);
    __half* Bs_h = (__half*)(sm + G2_BH);
    float* ssc = (float*)(sm + G2_SC);
    float* ssh = (float*)(sm + G2_SH);
    unsigned sb = smem_u32(sm);
    int tid = threadIdx.x, wid = tid >> 5, lane = tid & 31;
    int warp_m = wid & 1, warp_n = wid >> 1;
    int g = lane >> 2, tig = lane & 3;
    int r0 = blockIdx.x * 128;

    if (tid < 128) {
        double mu  = g_sum1[tid] / (double)Nn;
        double var = g_sq1[tid] / (double)Nn - mu * mu;
        double sc  = (double)bn1g[tid] * rsqrt(var + (double)EPSf);
        ssc[tid] = (float)sc;
        ssh[tid] = (float)((double)bn1b[tid] - mu * sc);
    }
    __syncthreads();

    {
        int row = tid >> 1, cb = (tid & 1) * 64;
        int grow = r0 + row;
        __half* dh = As_h + row * 136 + cb;
        __half* dl = As_l + row * 136 + cb;
        if (grow < Nn) {
            const float* srcrow = g_agg + (size_t)grow * 128 + cb;
            #pragma unroll
            for (int j = 0; j < 16; j++) {
                float4 v = *(const float4*)(srcrow + j * 4);
                int k = cb + j * 4;
                v.x = fmaf(v.x, ssc[k],     ssh[k]);
                v.y = fmaf(v.y, ssc[k + 1], ssh[k + 1]);
                v.z = fmaf(v.z, ssc[k + 2], ssh[k + 2]);
                v.w = fmaf(v.w, ssc[k + 3], ssh[k + 3]);
                split_store4(dh + j * 4, dl + j * 4, v);
            }
        } else {
            #pragma unroll
            for (int j = 0; j < 32; j++) {
                ((unsigned*)dh)[j] = 0u; ((unsigned*)dl)[j] = 0u;
            }
        }
    }

    int mrow0 = warp_m * 64, ncol0 = warp_n * 32;
    for (int nt = 0; nt < 4; nt++) {
        __syncthreads();
        load_B_tile(Bs_h, g_W1p_h + (size_t)nt * 16384, tid);
        __syncthreads();

        float acc[4][4][4];
        #pragma unroll
        for (int a = 0; a < 4; a++)
            #pragma unroll
            for (int b = 0; b < 4; b++)
                #pragma unroll
                for (int c = 0; c < 4; c++) acc[a][b][c] = 0.0f;
        mma_tile2A(acc, sb, sb + G2_AL, sb + G2_BH, lane, warp_m, warp_n);

        #pragma unroll
        for (int nf = 0; nf < 4; nf++) {
            int colg = nt * 128 + ncol0 + nf * 8 + tig * 2;
            float bb0 = b1[colg], bb1 = b1[colg + 1];
            #pragma unroll
            for (int mf = 0; mf < 4; mf++) {
                int row = r0 + mrow0 + mf * 16 + g;
                float v0 = acc[mf][nf][0] + bb0; v0 = (v0 > 0.f) ? v0 : 0.f;
                float v1 = acc[mf][nf][1] + bb1; v1 = (v1 > 0.f) ? v1 : 0.f;
                float v2 = acc[mf][nf][2] + bb0; v2 = (v2 > 0.f) ? v2 : 0.f;
                float v3 = acc[mf][nf][3] + bb1; v3 = (v3 > 0.f) ? v3 : 0.f;
                if (row < Nn)
                    *(__half2*)&g_hid_h[(size_t)row * 512 + colg] = __floats2half2_rn(v0, v1);
                if (row + 8 < Nn)
                    *(__half2*)&g_hid_h[(size_t)(row + 8) * 512 + colg] = __floats2half2_rn(v2, v3);
            }
        }
    }
}

// ---------------- gemm3: h2 = hid @ W2 + b2, 2-term B-split + fused BN2 stats ----------------
__global__ void __launch_bounds__(256) k_gemm3M(const float* __restrict__ b2) {
    extern __shared__ char sm[];
    __half* As_h = (__half*)sm;
    __half* Bs_h = (__half*)(sm + G3_BH);
    __half* Bs_l = (__half*)(sm + G3_BL);
    float* s_sum = (float*)(sm + G3_ST);
    float* s_sq  = (float*)(sm + G3_ST + 512);
    unsigned sb = smem_u32(sm);
    int tid = threadIdx.x, wid = tid >> 5, lane = tid & 31;
    int warp_m = wid & 1, warp_n = wid >> 1;
    int g = lane >> 2, tig = lane & 3;
    int r0 = blockIdx.x * 128;

    if (tid < 128) { s_sum[tid] = 0.0f; s_sq[tid] = 0.0f; }

    float acc[4][4][4];
    #pragma unroll
    for (int a = 0; a < 4; a++)
        #pragma unroll
        for (int b = 0; b < 4; b++)
            #pragma unroll
            for (int c = 0; c < 4; c++) acc[a][b][c] = 0.0f;

    for (int kc = 0; kc < 4; kc++) {
        __syncthreads();
        {
            int row = tid >> 1, cb = (tid & 1) * 64;
            int grow = r0 + row;
            uint4* dh = (uint4*)(As_h + row * 136 + cb);
            if (grow < Nn) {
                const uint4* shp = (const uint4*)(g_hid_h + (size_t)grow * 512 + kc * 128 + cb);
                #pragma unroll
                for (int j = 0; j < 8; j++) dh[j] = shp[j];
            } else {
                uint4 z = make_uint4(0, 0, 0, 0);
                #pragma unroll
                for (int j = 0; j < 8; j++) dh[j] = z;
            }
        }
        load_B_tile(Bs_h, g_W2p_h + (size_t)kc * 16384, tid);
        load_B_tile(Bs_l, g_W2p_l + (size_t)kc * 16384, tid);
        __syncthreads();
        mma_tile2B(acc, sb, sb + G3_BH, sb + G3_BL, lane, warp_m, warp_n);
    }

    int mrow0 = warp_m * 64, ncol0 = warp_n * 32;
    #pragma unroll
    for (int nf = 0; nf < 4; nf++) {
        int col = ncol0 + nf * 8 + tig * 2;
        float bb0 = b2[col], bb1 = b2[col + 1];
        float cs0 = 0.f, cq0 = 0.f, cs1 = 0.f, cq1 = 0.f;
        #pragma unroll
        for (int mf = 0; mf < 4; mf++) {
            int row = r0 + mrow0 + mf * 16 + g;
            float v0 = acc[mf][nf][0] + bb0, v1 = acc[mf][nf][1] + bb1;
            float v2 = acc[mf][nf][2] + bb0, v3 = acc[mf][nf][3] + bb1;
            if (row < Nn) {
                *(float2*)&g_h2[(size_t)row * 128 + col] = make_float2(v0, v1);
                cs0 += v0; cq0 += v0 * v0; cs1 += v1; cq1 += v1 * v1;
            }
            if (row + 8 < Nn) {
                *(float2*)&g_h2[(size_t)(row + 8) * 128 + col] = make_float2(v2, v3);
                cs0 += v2; cq0 += v2 * v2; cs1 += v3; cq1 += v3 * v3;
            }
        }
        atomicAdd(&s_sum[col], cs0);     atomicAdd(&s_sq[col], cq0);
        atomicAdd(&s_sum[col + 1], cs1); atomicAdd(&s_sq[col + 1], cq1);
    }
    __syncthreads();
    if (tid < 128) {
        atomicAdd(&g_sum2[tid], (double)s_sum[tid]);
        atomicAdd(&g_sq2[tid], (double)s_sq[tid]);
    }
}

// ---------------- out = BN2(h2) ----------------
__global__ void k_out(float* __restrict__ out,
        const float* __restrict__ bn2g, const float* __restrict__ bn2b) {
    __shared__ float s_sc[128], s_sh[128];
    int t = threadIdx.x;
    if (t < 128) {
        double mu  = g_sum2[t] / (double)Nn;
        double var = g_sq2[t] / (double)Nn - mu * mu;
        double sc  = (double)bn2g[t] * rsqrt(var + (double)EPSf);
        s_sc[t] = (float)sc;
        s_sh[t] = (float)((double)bn2b[t] - mu * sc);
    }
    __syncthreads();
    int i = blockIdx.x * blockDim.x + t;
    int total = Nn * Dd / 4;
    int stride = gridDim.x * blockDim.x;
    for (; i < total; i += stride) {
        int c4 = (i & 31) * 4;
        float4 v  = ((const float4*)g_h2)[i];
        float4 sc = *(const float4*)(s_sc + c4);
        float4 sh = *(const float4*)(s_sh + c4);
        v.x = v.x * sc.x + sh.x;
        v.y = v.y * sc.y + sh.y;
        v.z = v.z * sc.z + sh.z;
        v.w = v.w * sc.w + sh.w;
        ((float4*)out)[i] = v;
    }
}

// ---------------- launch ----------------
extern "C" void kernel_launch(void* const* d_in, const int* in_sizes, int n_in,
                              void* d_out, int out_size) {
    const float* x        = (const float*)d_in[0];
    const int*   src      = (const int*)d_in[1];
    const int*   dst      = (const int*)d_in[2];
    const float* W        = (const float*)d_in[3];
    const float* attn_l   = (const float*)d_in[4];
    const float* attn_r   = (const float*)d_in[5];
    const float* bias_gat = (const float*)d_in[6];
    const float* bn1g     = (const float*)d_in[7];
    const float* bn1b     = (const float*)d_in[8];
    const float* W1       = (const float*)d_in[9];
    const float* b1       = (const float*)d_in[10];
    const float* W2       = (const float*)d_in[11];
    const float* b2       = (const float*)d_in[12];
    const float* bn2g     = (const float*)d_in[13];
    const float* bn2b     = (const float*)d_in[14];
    float* out = (float*)d_out;

    static int configured = 0;
    if (!configured) {
        cudaFuncSetAttribute(k_featM,  cudaFuncAttributeMaxDynamicSharedMemorySize, SM_FEAT);
        cudaFuncSetAttribute(k_gemm2M, cudaFuncAttributeMaxDynamicSharedMemorySize, SM_G2);
        cudaFuncSetAttribute(k_gemm3M, cudaFuncAttributeMaxDynamicSharedMemorySize, SM_G3);
        configured = 1;
    }

    k_prepAll<<<dim3(10, 8), 256>>>(W, W1, W2);
    k_hist<<<(Ee + 255) / 256, 256>>>(dst);
    k_allocScan<<<(Nn + 1023) / 1024, 1024>>>();
    k_scatter<<<(Ee + 255) / 256, 256>>>(src, dst);
    k_featM<<<MT, 256, SM_FEAT>>>(x, attn_l, attn_r);
    k_agg<<<(Nn + 7) / 8, 256>>>(bias_gat);
    k_stats1<<<512, 128>>>();
    k_gemm2M<<<MT, 256, SM_G2>>>(b1, bn1g, bn1b);
    k_gemm3M<<<MT, 256, SM_G3>>>(b2);
    k_out<<<2048, 256>>>(out, bn2g, bn2b);
}

// round 17
// speedup vs baseline: 1.0854x; 1.0234x over previous
#include <cuda_runtime.h>
#include <cuda_fp16.h>
#include <cuda_bf16.h>

// Problem constants
#define Nn   50000
#define Ee   800000
#define Dd   128
#define Hh   8
#define HIDd 512
#define SLOPEf 0.2f
#define EPSf 1e-5f
#define MT   391          // ceil(50000/128) row tiles

// featM smem layout (3-term: Ah Al Bh Bl)
#define OFF_AL 34816
#define OFF_BH 69632
#define OFF_BL 104448
#define SM_FEAT 139264
// gemm2 smem layout (Ah Al Bh + BN consts)
#define G2_AL 34816
#define G2_BH 69632
#define G2_SC 104448
#define G2_SH 104960
#define SM_G2 105472
// gemm3 smem layout (Ah Bh Bl)
#define G3_BH 34816
#define G3_BL 69632
#define SM_G3 104448

// ---------------- device scratch ----------------
__device__ __align__(16) float    g_feat[Nn * Dd];
__device__ __align__(16) float    g_el[Nn * Hh];
__device__ __align__(16) float    g_er[Nn * Hh];
__device__ __align__(16) float    g_agg[Nn * Dd];
__device__ __align__(16) float    g_h2[Nn * Dd];
// CSR
__device__ int g_deg[Nn];
__device__ int g_startA[Nn];
__device__ int g_cursor[Nn];
__device__ int g_csrc[Ee];
__device__ int g_total;
// prepared fp16-split weights, [tile][n][k] k-contiguous
__device__ __align__(16) __half g_Wp_h[Dd * Dd],    g_Wp_l[Dd * Dd];
__device__ __align__(16) __half g_W1p_h[Dd * HIDd];
__device__ __align__(16) __half g_W2p_h[HIDd * Dd], g_W2p_l[HIDd * Dd];
// hidden activations, fp16 hi plane only, [row][512]
__device__ __align__(16) __half g_hid_h[(size_t)Nn * HIDd];
__device__ double g_sum1[Dd], g_sq1[Dd], g_sum2[Dd], g_sq2[Dd];

// ---------------- small helpers ----------------
__device__ __forceinline__ unsigned smem_u32(const void* p) {
    unsigned a;
    asm("{ .reg .u64 t; cvta.to.shared.u64 t, %1; cvt.u32.u64 %0, t; }" : "=r"(a) : "l"(p));
    return a;
}
__device__ __forceinline__ void split_store4(__half* dh, __half* dl, float4 v) {
    __half2 h0 = __floats2half2_rn(v.x, v.y);
    __half2 h1 = __floats2half2_rn(v.z, v.w);
    float2 f0 = __half22float2(h0);
    float2 f1 = __half22float2(h1);
    __half2 l0 = __floats2half2_rn(v.x - f0.x, v.y - f0.y);
    __half2 l1 = __floats2half2_rn(v.z - f1.x, v.w - f1.y);
    *(__half2*)(dh)     = h0;  *(__half2*)(dh + 2) = h1;
    *(__half2*)(dl)     = l0;  *(__half2*)(dl + 2) = l1;
}

// ---------------- mma.sync primitives ----------------
#define LDSM4(r, a) asm volatile("ldmatrix.sync.aligned.m8n8.x4.shared.b16 {%0,%1,%2,%3}, [%4];" \
    : "=r"((r)[0]), "=r"((r)[1]), "=r"((r)[2]), "=r"((r)[3]) : "r"(a))
#define LDSM2(r, a) asm volatile("ldmatrix.sync.aligned.m8n8.x2.shared.b16 {%0,%1}, [%2];" \
    : "=r"((r)[0]), "=r"((r)[1]) : "r"(a))

__device__ __forceinline__ void mma_f16(float c[4], const unsigned a[4], const unsigned b[2]) {
    asm volatile("mma.sync.aligned.m16n8k16.row.col.f32.f16.f16.f32 "
        "{%0,%1,%2,%3}, {%4,%5,%6,%7}, {%8,%9}, {%0,%1,%2,%3};"
        : "+f"(c[0]), "+f"(c[1]), "+f"(c[2]), "+f"(c[3])
        : "r"(a[0]), "r"(a[1]), "r"(a[2]), "r"(a[3]), "r"(b[0]), "r"(b[1]));
}

__device__ __forceinline__ unsigned a_frag_off(int mrow0, int mf, int lane, int ks) {
    return 2u * ((unsigned)(mrow0 + mf * 16 + (lane & 15)) * 136u
                 + (unsigned)((lane >> 4) * 8) + (unsigned)ks * 16u);
}
__device__ __forceinline__ unsigned b_frag_off(int ncol0, int nf, int lane, int ks) {
    return 2u * ((unsigned)(ncol0 + nf * 8 + (lane & 7)) * 136u
                 + (unsigned)(((lane >> 3) & 1) * 8) + (unsigned)ks * 16u);
}

// 3-term: (Ah+Al)·Bh + Ah·Bl   (featM)
__device__ __forceinline__ void mma_tile3(float acc[4][4][4], unsigned aAh, unsigned aAl,
                                          unsigned aBh, unsigned aBl, int lane,
                                          int warp_m, int warp_n) {
    int mrow0 = warp_m * 64, ncol0 = warp_n * 32;
    #pragma unroll
    for (int ks = 0; ks < 8; ks++) {
        unsigned ah[4][4], al[4][4], bh[4][2], bl[4][2];
        #pragma unroll
        for (int mf = 0; mf < 4; mf++) {
            unsigned off = a_frag_off(mrow0, mf, lane, ks);
            LDSM4(ah[mf], aAh + off);
            LDSM4(al[mf], aAl + off);
        }
        #pragma unroll
        for (int nf = 0; nf < 4; nf++) {
            unsigned off = b_frag_off(ncol0, nf, lane, ks);
            LDSM2(bh[nf], aBh + off);
            LDSM2(bl[nf], aBl + off);
        }
        #pragma unroll
        for (int mf = 0; mf < 4; mf++)
            #pragma unroll
            for (int nf = 0; nf < 4; nf++) {
                mma_f16(acc[mf][nf], ah[mf], bh[nf]);
                mma_f16(acc[mf][nf], al[mf], bh[nf]);
                mma_f16(acc[mf][nf], ah[mf], bl[nf]);
            }
    }
}

// 2-term A-split: (Ah+Al)·Bh   (gemm2)
__device__ __forceinline__ void mma_tile2A(float acc[4][4][4], unsigned aAh, unsigned aAl,
                                           unsigned aBh, int lane, int warp_m, int warp_n) {
    int mrow0 = warp_m * 64, ncol0 = warp_n * 32;
    #pragma unroll
    for (int ks = 0; ks < 8; ks++) {
        unsigned ah[4][4], al[4][4], bh[4][2];
        #pragma unroll
        for (int mf = 0; mf < 4; mf++) {
            unsigned off = a_frag_off(mrow0, mf, lane, ks);
            LDSM4(ah[mf], aAh + off);
            LDSM4(al[mf], aAl + off);
        }
        #pragma unroll
        for (int nf = 0; nf < 4; nf++)
            LDSM2(bh[nf], aBh + b_frag_off(ncol0, nf, lane, ks));
        #pragma unroll
        for (int mf = 0; mf < 4; mf++)
            #pragma unroll
            for (int nf = 0; nf < 4; nf++) {
                mma_f16(acc[mf][nf], ah[mf], bh[nf]);
                mma_f16(acc[mf][nf], al[mf], bh[nf]);
            }
    }
}

// 2-term B-split: Ah·(Bh+Bl)   (gemm3)
__device__ __forceinline__ void mma_tile2B(float acc[4][4][4], unsigned aAh,
                                           unsigned aBh, unsigned aBl, int lane,
                                           int warp_m, int warp_n) {
    int mrow0 = warp_m * 64, ncol0 = warp_n * 32;
    #pragma unroll
    for (int ks = 0; ks < 8; ks++) {
        unsigned ah[4][4], bh[4][2], bl[4][2];
        #pragma unroll
        for (int mf = 0; mf < 4; mf++)
            LDSM4(ah[mf], aAh + a_frag_off(mrow0, mf, lane, ks));
        #pragma unroll
        for (int nf = 0; nf < 4; nf++) {
            unsigned off = b_frag_off(ncol0, nf, lane, ks);
            LDSM2(bh[nf], aBh + off);
            LDSM2(bl[nf], aBl + off);
        }
        #pragma unroll
        for (int mf = 0; mf < 4; mf++)
            #pragma unroll
            for (int nf = 0; nf < 4; nf++) {
                mma_f16(acc[mf][nf], ah[mf], bh[nf]);
                mma_f16(acc[mf][nf], ah[mf], bl[nf]);
            }
    }
}

__device__ __forceinline__ void load_B_tile(__half* Bs, const __half* gB, int tid) {
    for (int i = tid; i < 128 * 16; i += 256) {
        int n = i >> 4, q = i & 15;
        ((uint4*)(Bs + n * 136))[q] = ((const uint4*)(gB + n * 128))[q];
    }
}

// ---------------- init ----------------
__global__ void k_init() {
    int i = blockIdx.x * blockDim.x + threadIdx.x;
    int stride = gridDim.x * blockDim.x;
    for (int j = i; j < Nn; j += stride) g_deg[j] = 0;
    if (i < Dd) { g_sum1[i] = 0.0; g_sq1[i] = 0.0; g_sum2[i] = 0.0; g_sq2[i] = 0.0; }
    if (i == 0) g_total = 0;
}

// ---------------- merged weight prep ----------------
// blockIdx.x: 0 -> W (hi+lo), 1..4 -> W1 nt (hi only), 5..8 -> W2 kc (hi+lo)
__global__ void k_prepAll(const float* __restrict__ W, const float* __restrict__ W1,
                          const float* __restrict__ W2) {
    int t = blockIdx.x;
    const float* src; __half *dh, *dl; int Ncols, kc, nt, KC;
    if (t == 0)      { src = W;  dh = g_Wp_h;  dl = g_Wp_l;  Ncols = Dd;   kc = 0;     nt = 0;     KC = 1; }
    else if (t <= 4) { src = W1; dh = g_W1p_h; dl = 0;       Ncols = HIDd; kc = 0;     nt = t - 1; KC = 1; }
    else             { src = W2; dh = g_W2p_h; dl = g_W2p_l; Ncols = Dd;   kc = t - 5; nt = 0;     KC = 4; }
    size_t tb = ((size_t)nt * KC + kc) * 16384;
    int z0 = blockIdx.y * 2048, z1 = z0 + 2048;
    for (int i = z0 + threadIdx.x; i < z1; i += blockDim.x) {
        int n = i >> 7, k = i & 127;
        float v = src[(size_t)(kc * 128 + k) * Ncols + nt * 128 + n];
        __half h = __float2half(v);
        dh[tb + (size_t)n * 128 + k] = h;
        if (dl) dl[tb + (size_t)n * 128 + k] = __float2half(v - __half2float(h));
    }
}

// ---------------- feat = x @ W (MMA, 3-term) + el/er epilogue ----------------
__global__ void __launch_bounds__(256, 1) k_featM(const float* __restrict__ x,
        const float* __restrict__ attn_l, const float* __restrict__ attn_r) {
    extern __shared__ char sm[];
    __half* As_h = (__half*)sm;
    __half* As_l = (__half*)(sm + OFF_AL);
    __half* Bs_h = (__half*)(sm + OFF_BH);
    __half* Bs_l = (__half*)(sm + OFF_BL);
    unsigned sb = smem_u32(sm);
    int tid = threadIdx.x, wid = tid >> 5, lane = tid & 31;
    int warp_m = wid & 1, warp_n = wid >> 1;
    int g = lane >> 2, tig = lane & 3;
    int r0 = blockIdx.x * 128;

    {
        int row = tid >> 1, cb = (tid & 1) * 64;
        int grow = r0 + row;
        __half* dh = As_h + row * 136 + cb;
        __half* dl = As_l + row * 136 + cb;
        if (grow < Nn) {
            const float* srcrow = x + (size_t)grow * 128 + cb;
            #pragma unroll
            for (int j = 0; j < 16; j++)
                split_store4(dh + j * 4, dl + j * 4, *(const float4*)(srcrow + j * 4));
        } else {
            #pragma unroll
            for (int j = 0; j < 32; j++) {
                ((unsigned*)dh)[j] = 0u; ((unsigned*)dl)[j] = 0u;
            }
        }
    }
    load_B_tile(Bs_h, g_Wp_h, tid);
    load_B_tile(Bs_l, g_Wp_l, tid);
    __syncthreads();

    float acc[4][4][4];
    #pragma unroll
    for (int a = 0; a < 4; a++)
        #pragma unroll
        for (int b = 0; b < 4; b++)
            #pragma unroll
            for (int c = 0; c < 4; c++) acc[a][b][c] = 0.0f;
    mma_tile3(acc, sb, sb + OFF_AL, sb + OFF_BH, sb + OFF_BL, lane, warp_m, warp_n);

    int mrow0 = warp_m * 64, ncol0 = warp_n * 32;
    float attl[4][2], attr[4][2];
    #pragma unroll
    for (int nf = 0; nf < 4; nf++) {
        int col = ncol0 + nf * 8 + tig * 2;
        attl[nf][0] = attn_l[col]; attl[nf][1] = attn_l[col + 1];
        attr[nf][0] = attn_r[col]; attr[nf][1] = attn_r[col + 1];
    }
    float sl[4][2][2], sr[4][2][2];
    #pragma unroll
    for (int mf = 0; mf < 4; mf++)
        #pragma unroll
        for (int rh = 0; rh < 2; rh++)
            #pragma unroll
            for (int h2 = 0; h2 < 2; h2++) { sl[mf][rh][h2] = 0.f; sr[mf][rh][h2] = 0.f; }

    #pragma unroll
    for (int mf = 0; mf < 4; mf++) {
        #pragma unroll
        for (int nf = 0; nf < 4; nf++) {
            int col = ncol0 + nf * 8 + tig * 2;
            int row = r0 + mrow0 + mf * 16 + g;
            float c0 = acc[mf][nf][0], c1 = acc[mf][nf][1];
            float c2 = acc[mf][nf][2], c3 = acc[mf][nf][3];
            if (row < Nn)      *(float2*)&g_feat[(size_t)row * 128 + col] = make_float2(c0, c1);
            if (row + 8 < Nn)  *(float2*)&g_feat[(size_t)(row + 8) * 128 + col] = make_float2(c2, c3);
            int h2 = nf >> 1;
            sl[mf][0][h2] += c0 * attl[nf][0] + c1 * attl[nf][1];
            sl[mf][1][h2] += c2 * attl[nf][0] + c3 * attl[nf][1];
            sr[mf][0][h2] += c0 * attr[nf][0] + c1 * attr[nf][1];
            sr[mf][1][h2] += c2 * attr[nf][0] + c3 * attr[nf][1];
        }
    }
    #pragma unroll
    for (int mf = 0; mf < 4; mf++)
        #pragma unroll
        for (int rh = 0; rh < 2; rh++)
            #pragma unroll
            for (int h2 = 0; h2 < 2; h2++) {
                float vl = sl[mf][rh][h2], vr = sr[mf][rh][h2];
                vl += __shfl_down_sync(0xffffffffu, vl, 1, 4);
                vl += __shfl_down_sync(0xffffffffu, vl, 2, 4);
                vr += __shfl_down_sync(0xffffffffu, vr, 1, 4);
                vr += __shfl_down_sync(0xffffffffu, vr, 2, 4);
                if (tig == 0) {
                    int row = r0 + mrow0 + mf * 16 + g + rh * 8;
                    if (row < Nn) {
                        int h = warp_n * 2 + h2;
                        g_el[row * 8 + h] = vl;
                        g_er[row * 8 + h] = vr;
                    }
                }
            }
}

// ---------------- CSR build ----------------
__global__ void k_hist(const int* __restrict__ dst) {
    int i = blockIdx.x * blockDim.x + threadIdx.x;
    if (i < Ee) atomicAdd(&g_deg[dst[i]], 1);
}

__global__ void __launch_bounds__(1024) k_allocScan() {
    __shared__ int swsum[32];
    __shared__ int sbase;
    int i = blockIdx.x * blockDim.x + threadIdx.x;
    int wid = threadIdx.x >> 5, lane = threadIdx.x & 31;
    int deg = (i < Nn) ? g_deg[i] : 0;
    int v = deg;
    #pragma unroll
    for (int off = 1; off < 32; off <<= 1) {
        int t = __shfl_up_sync(0xffffffffu, v, off);
        if (lane >= off) v += t;
    }
    if (lane == 31) swsum[wid] = v;
    __syncthreads();
    if (wid == 0) {
        int w = swsum[lane];
        int wv = w;
        #pragma unroll
        for (int off = 1; off < 32; off <<= 1) {
            int t = __shfl_up_sync(0xffffffffu, wv, off);
            if (lane >= off) wv += t;
        }
        swsum[lane] = wv - w;
        if (lane == 31) sbase = atomicAdd(&g_total, wv);
    }
    __syncthreads();
    if (i < Nn) {
        int start = sbase + swsum[wid] + (v - deg);
        g_startA[i] = start;
        g_cursor[i] = start;
    }
}

__global__ void k_scatter(const int* __restrict__ src, const int* __restrict__ dst) {
    int i = blockIdx.x * blockDim.x + threadIdx.x;
    if (i >= Ee) return;
    int p = atomicAdd(&g_cursor[dst[i]], 1);
    g_csrc[p] = src[i];
}

// ---------------- fused softmax + aggregate: warp per dst node (barrier-free) ----------------
#define ACAP 64
__global__ void __launch_bounds__(256) k_agg(const float* __restrict__ bias) {
    __shared__ int   ssrc[8][ACAP];
    __shared__ float salpha[8][ACAP][8];
    __shared__ float smInv[8][8];
    int wid = threadIdx.x >> 5, lane = threadIdx.x & 31;
    int d = blockIdx.x * 8 + wid;
    if (d >= Nn) return;
    float4 b4 = *(const float4*)(bias + lane * 4);

    int start = g_startA[d], deg = g_deg[d];
    float4 er0 = *(const float4*)(g_er + d * 8);
    float4 er1 = *(const float4*)(g_er + d * 8 + 4);

    float ds[8];
    #pragma unroll
    for (int h = 0; h < 8; h++) ds[h] = 0.0f;
    for (int j = lane; j < deg; j += 32) {
        int s = g_csrc[start + j];
        float4 l0 = *(const float4*)(g_el + s * 8);
        float4 l1 = *(const float4*)(g_el + s * 8 + 4);
        float e[8] = { l0.x + er0.x, l0.y + er0.y, l0.z + er0.z, l0.w + er0.w,
                       l1.x + er1.x, l1.y + er1.y, l1.z + er1.z, l1.w + er1.w };
        float ee[8];
        #pragma unroll
        for (int h = 0; h < 8; h++) {
            float v = e[h];
            v = (v > 0.0f) ? v : SLOPEf * v;
            ee[h] = __expf(v);
            ds[h] += ee[h];
        }
        if (j < ACAP) {
            ssrc[wid][j] = s;
            ((float4*)salpha[wid][j])[0] = make_float4(ee[0], ee[1], ee[2], ee[3]);
            ((float4*)salpha[wid][j])[1] = make_float4(ee[4], ee[5], ee[6], ee[7]);
        }
    }
    #pragma unroll
    for (int off = 16; off > 0; off >>= 1)
        #pragma unroll
        for (int h = 0; h < 8; h++)
            ds[h] += __shfl_xor_sync(0xffffffffu, ds[h], off);
    #pragma unroll
    for (int h = 0; h < 8; h++)
        if (lane == h) smInv[wid][h] = (ds[h] > 0.0f) ? (1.0f / ds[h]) : 0.0f;
    __syncwarp();

    int hh = lane >> 2;
    float inv = smInv[wid][hh];
    float ax = 0.f, ay = 0.f, az = 0.f, aw = 0.f;
    int jcap = (deg < ACAP) ? deg : ACAP;
    int j = 0;
    for (; j + 4 <= jcap; j += 4) {
        int s0 = ssrc[wid][j],     s1 = ssrc[wid][j + 1];
        int s2 = ssrc[wid][j + 2], s3 = ssrc[wid][j + 3];
        float a0 = salpha[wid][j][hh]     * inv;
        float a1 = salpha[wid][j + 1][hh] * inv;
        float a2 = salpha[wid][j + 2][hh] * inv;
        float a3 = salpha[wid][j + 3][hh] * inv;
        float4 f0 = *(const float4*)(g_feat + (size_t)s0 * 128 + lane * 4);
        float4 f1 = *(const float4*)(g_feat + (size_t)s1 * 128 + lane * 4);
        float4 f2 = *(const float4*)(g_feat + (size_t)s2 * 128 + lane * 4);
        float4 f3 = *(const float4*)(g_feat + (size_t)s3 * 128 + lane * 4);
        ax += f0.x * a0 + f1.x * a1 + f2.x * a2 + f3.x * a3;
        ay += f0.y * a0 + f1.y * a1 + f2.y * a2 + f3.y * a3;
        az += f0.z * a0 + f1.z * a1 + f2.z * a2 + f3.z * a3;
        aw += f0.w * a0 + f1.w * a1 + f2.w * a2 + f3.w * a3;
    }
    for (; j < jcap; j++) {
        int s0 = ssrc[wid][j];
        float a0 = salpha[wid][j][hh] * inv;
        float4 f0 = *(const float4*)(g_feat + (size_t)s0 * 128 + lane * 4);
        ax += f0.x * a0; ay += f0.y * a0; az += f0.z * a0; aw += f0.w * a0;
    }
    for (; j < deg; j++) {
        int s0 = g_csrc[start + j];
        float erh = g_er[d * 8 + hh];
        float e = g_el[s0 * 8 + hh] + erh;
        e = (e > 0.0f) ? e : SLOPEf * e;
        float a0 = __expf(e) * inv;
        float4 f0 = *(const float4*)(g_feat + (size_t)s0 * 128 + lane * 4);
        ax += f0.x * a0; ay += f0.y * a0; az += f0.z * a0; aw += f0.w * a0;
    }
    *(float4*)(g_agg + (size_t)d * 128 + lane * 4) =
        make_float4(ax + b4.x, ay + b4.y, az + b4.z, aw + b4.w);
}

// ---------------- BN1 stats ----------------
__global__ void k_stats1() {
    int c = threadIdx.x;
    double s = 0.0, s2 = 0.0;
    for (int r = blockIdx.x; r < Nn; r += gridDim.x) {
        float v = g_agg[(size_t)r * Dd + c];
        s += v; s2 += (double)v * v;
    }
    atomicAdd(&g_sum1[c], s);
    atomicAdd(&g_sq1[c], s2);
}

// ---------------- gemm2: hid = relu(BN1(h1) @ W1 + b1), 2-term A-split ----------------
__global__ void __launch_bounds__(256) k_gemm2M(const float* __restrict__ b1,
        const float* __restrict__ bn1g, const float* __restrict__ bn1b) {
    extern __shared__ char sm[];
    __half* As_h = (__half*)sm;
    __half* As_l = (__half*)(sm + G2_AL);
    __half* Bs_h = (__half*)(sm + G2_BH);
    float* ssc = (float*)(sm + G2_SC);
    float* ssh = (float*)(sm + G2_SH);
    unsigned sb = smem_u32(sm);
    int tid = threadIdx.x, wid = tid >> 5, lane = tid & 31;
    int warp_m = wid & 1, warp_n = wid >> 1;
    int g = lane >> 2, tig = lane & 3;
    int r0 = blockIdx.x * 128;

    if (tid < 128) {
        double mu  = g_sum1[tid] / (double)Nn;
        double var = g_sq1[tid] / (double)Nn - mu * mu;
        double sc  = (double)bn1g[tid] * rsqrt(var + (double)EPSf);
        ssc[tid] = (float)sc;
        ssh[tid] = (float)((double)bn1b[tid] - mu * sc);
    }
    __syncthreads();

    {
        int row = tid >> 1, cb = (tid & 1) * 64;
        int grow = r0 + row;
        __half* dh = As_h + row * 136 + cb;
        __half* dl = As_l + row * 136 + cb;
        if (grow < Nn) {
            const float* srcrow = g_agg + (size_t)grow * 128 + cb;
            #pragma unroll
            for (int j = 0; j < 16; j++) {
                float4 v = *(const float4*)(srcrow + j * 4);
                int k = cb + j * 4;
                v.x = fmaf(v.x, ssc[k],     ssh[k]);
                v.y = fmaf(v.y, ssc[k + 1], ssh[k + 1]);
                v.z = fmaf(v.z, ssc[k + 2], ssh[k + 2]);
                v.w = fmaf(v.w, ssc[k + 3], ssh[k + 3]);
                split_store4(dh + j * 4, dl + j * 4, v);
            }
        } else {
            #pragma unroll
            for (int j = 0; j < 32; j++) {
                ((unsigned*)dh)[j] = 0u; ((unsigned*)dl)[j] = 0u;
            }
        }
    }

    int mrow0 = warp_m * 64, ncol0 = warp_n * 32;
    for (int nt = 0; nt < 4; nt++) {
        __syncthreads();
        load_B_tile(Bs_h, g_W1p_h + (size_t)nt * 16384, tid);
        __syncthreads();

        float acc[4][4][4];
        #pragma unroll
        for (int a = 0; a < 4; a++)
            #pragma unroll
            for (int b = 0; b < 4; b++)
                #pragma unroll
                for (int c = 0; c < 4; c++) acc[a][b][c] = 0.0f;
        mma_tile2A(acc, sb, sb + G2_AL, sb + G2_BH, lane, warp_m, warp_n);

        #pragma unroll
        for (int nf = 0; nf < 4; nf++) {
            int colg = nt * 128 + ncol0 + nf * 8 + tig * 2;
            float bb0 = b1[colg], bb1 = b1[colg + 1];
            #pragma unroll
            for (int mf = 0; mf < 4; mf++) {
                int row = r0 + mrow0 + mf * 16 + g;
                float v0 = acc[mf][nf][0] + bb0; v0 = (v0 > 0.f) ? v0 : 0.f;
                float v1 = acc[mf][nf][1] + bb1; v1 = (v1 > 0.f) ? v1 : 0.f;
                float v2 = acc[mf][nf][2] + bb0; v2 = (v2 > 0.f) ? v2 : 0.f;
                float v3 = acc[mf][nf][3] + bb1; v3 = (v3 > 0.f) ? v3 : 0.f;
                if (row < Nn)
                    *(__half2*)&g_hid_h[(size_t)row * 512 + colg] = __floats2half2_rn(v0, v1);
                if (row + 8 < Nn)
                    *(__half2*)&g_hid_h[(size_t)(row + 8) * 512 + colg] = __floats2half2_rn(v2, v3);
            }
        }
    }
}

// ---------------- gemm3: h2 = hid @ W2 + b2, 2-term B-split (K=512 in 4 chunks) ----------------
__global__ void __launch_bounds__(256) k_gemm3M(const float* __restrict__ b2) {
    extern __shared__ char sm[];
    __half* As_h = (__half*)sm;
    __half* Bs_h = (__half*)(sm + G3_BH);
    __half* Bs_l = (__half*)(sm + G3_BL);
    unsigned sb = smem_u32(sm);
    int tid = threadIdx.x, wid = tid >> 5, lane = tid & 31;
    int warp_m = wid & 1, warp_n = wid >> 1;
    int g = lane >> 2, tig = lane & 3;
    int r0 = blockIdx.x * 128;

    float acc[4][4][4];
    #pragma unroll
    for (int a = 0; a < 4; a++)
        #pragma unroll
        for (int b = 0; b < 4; b++)
            #pragma unroll
            for (int c = 0; c < 4; c++) acc[a][b][c] = 0.0f;

    for (int kc = 0; kc < 4; kc++) {
        __syncthreads();
        {
            int row = tid >> 1, cb = (tid & 1) * 64;
            int grow = r0 + row;
            uint4* dh = (uint4*)(As_h + row * 136 + cb);
            if (grow < Nn) {
                const uint4* shp = (const uint4*)(g_hid_h + (size_t)grow * 512 + kc * 128 + cb);
                #pragma unroll
                for (int j = 0; j < 8; j++) dh[j] = shp[j];
            } else {
                uint4 z = make_uint4(0, 0, 0, 0);
                #pragma unroll
                for (int j = 0; j < 8; j++) dh[j] = z;
            }
        }
        load_B_tile(Bs_h, g_W2p_h + (size_t)kc * 16384, tid);
        load_B_tile(Bs_l, g_W2p_l + (size_t)kc * 16384, tid);
        __syncthreads();
        mma_tile2B(acc, sb, sb + G3_BH, sb + G3_BL, lane, warp_m, warp_n);
    }

    int mrow0 = warp_m * 64, ncol0 = warp_n * 32;
    #pragma unroll
    for (int nf = 0; nf < 4; nf++) {
        int col = ncol0 + nf * 8 + tig * 2;
        float bb0 = b2[col], bb1 = b2[col + 1];
        #pragma unroll
        for (int mf = 0; mf < 4; mf++) {
            int row = r0 + mrow0 + mf * 16 + g;
            if (row < Nn)
                *(float2*)&g_h2[(size_t)row * 128 + col] =
                    make_float2(acc[mf][nf][0] + bb0, acc[mf][nf][1] + bb1);
            if (row + 8 < Nn)
                *(float2*)&g_h2[(size_t)(row + 8) * 128 + col] =
                    make_float2(acc[mf][nf][2] + bb0, acc[mf][nf][3] + bb1);
        }
    }
}

// ---------------- BN2 stats / out ----------------
__global__ void k_stats2() {
    int c = threadIdx.x;
    double s = 0.0, s2 = 0.0;
    for (int r = blockIdx.x; r < Nn; r += gridDim.x) {
        float v = g_h2[(size_t)r * Dd + c];
        s += v; s2 += (double)v * v;
    }
    atomicAdd(&g_sum2[c], s);
    atomicAdd(&g_sq2[c], s2);
}
__global__ void k_out(float* __restrict__ out,
        const float* __restrict__ bn2g, const float* __restrict__ bn2b) {
    __shared__ float s_sc[128], s_sh[128];
    int t = threadIdx.x;
    if (t < 128) {
        double mu  = g_sum2[t] / (double)Nn;
        double var = g_sq2[t] / (double)Nn - mu * mu;
        double sc  = (double)bn2g[t] * rsqrt(var + (double)EPSf);
        s_sc[t] = (float)sc;
        s_sh[t] = (float)((double)bn2b[t] - mu * sc);
    }
    __syncthreads();
    int i = blockIdx.x * blockDim.x + t;
    int total = Nn * Dd / 4;
    int stride = gridDim.x * blockDim.x;
    for (; i < total; i += stride) {
        int c4 = (i & 31) * 4;
        float4 v  = ((const float4*)g_h2)[i];
        float4 sc = *(const float4*)(s_sc + c4);
        float4 sh = *(const float4*)(s_sh + c4);
        v.x = v.x * sc.x + sh.x;
        v.y = v.y * sc.y + sh.y;
        v.z = v.z * sc.z + sh.z;
        v.w = v.w * sc.w + sh.w;
        ((float4*)out)[i] = v;
    }
}

// ---------------- launch (serial, single stream — streams removed) ----------------
extern "C" void kernel_launch(void* const* d_in, const int* in_sizes, int n_in,
                              void* d_out, int out_size) {
    const float* x        = (const float*)d_in[0];
    const int*   src      = (const int*)d_in[1];
    const int*   dst      = (const int*)d_in[2];
    const float* W        = (const float*)d_in[3];
    const float* attn_l   = (const float*)d_in[4];
    const float* attn_r   = (const float*)d_in[5];
    const float* bias_gat = (const float*)d_in[6];
    const float* bn1g     = (const float*)d_in[7];
    const float* bn1b     = (const float*)d_in[8];
    const float* W1       = (const float*)d_in[9];
    const float* b1       = (const float*)d_in[10];
    const float* W2       = (const float*)d_in[11];
    const float* b2       = (const float*)d_in[12];
    const float* bn2g     = (const float*)d_in[13];
    const float* bn2b     = (const float*)d_in[14];
    float* out = (float*)d_out;

    static int configured = 0;
    if (!configured) {
        cudaFuncSetAttribute(k_featM,  cudaFuncAttributeMaxDynamicSharedMemorySize, SM_FEAT);
        cudaFuncSetAttribute(k_gemm2M, cudaFuncAttributeMaxDynamicSharedMemorySize, SM_G2);
        cudaFuncSetAttribute(k_gemm3M, cudaFuncAttributeMaxDynamicSharedMemorySize, SM_G3);
        configured = 1;
    }

    k_init<<<256, 256>>>();
    k_prepAll<<<dim3(9, 8), 256>>>(W, W1, W2);
    k_hist<<<(Ee + 255) / 256, 256>>>(dst);
    k_allocScan<<<(Nn + 1023) / 1024, 1024>>>();
    k_scatter<<<(Ee + 255) / 256, 256>>>(src, dst);
    k_featM<<<MT, 256, SM_FEAT>>>(x, attn_l, attn_r);
    k_agg<<<(Nn + 7) / 8, 256>>>(bias_gat);
    k_stats1<<<512, 128>>>();
    k_gemm2M<<<MT, 256, SM_G2>>>(b1, bn1g, bn1b);
    k_gemm3M<<<MT, 256, SM_G3>>>(b2);
    k_stats2<<<512, 128>>>();
    k_out<<<2048, 256>>>(out, bn2g, bn2b);
}